// round 5
// baseline (speedup 1.0000x reference)
#include <cuda_runtime.h>
#include <cuda_bf16.h>
#include <cstdint>

// Problem constants (fixed shapes per reference): B=64, N=4096, K=128
#define KDIM 128

// Scratch for the unique-relabel (no allocations allowed -> __device__ globals)
__device__ int g_present[KDIM];
__device__ int g_rank[KDIM];

// ---------------------------------------------------------------------------
// Kernel 1: zero the presence bitmap
// ---------------------------------------------------------------------------
__global__ void k_zero_present() {
    if (threadIdx.x < KDIM) g_present[threadIdx.x] = 0;
}

// ---------------------------------------------------------------------------
// Kernel 2: scatter presence from labels C (benign write races, all write 1)
// ---------------------------------------------------------------------------
__global__ void k_scatter_present(const int* __restrict__ C, int n) {
    int i = blockIdx.x * blockDim.x + threadIdx.x;
    if (i < n) {
        int c = C[i];
        g_present[c] = 1;
    }
}

// ---------------------------------------------------------------------------
// Kernel 3: rank[v] = #unique labels < v  (exclusive prefix sum, 1 block)
// ---------------------------------------------------------------------------
__global__ void k_rank() {
    __shared__ int p[KDIM];
    int t = threadIdx.x;
    p[t] = g_present[t];
    __syncthreads();
    int r = 0;
    #pragma unroll 4
    for (int j = 0; j < t; ++j) r += p[j];
    g_rank[t] = r;
}

// ---------------------------------------------------------------------------
// Kernel 4: main. One warp per row (b,i). K=128 -> 4 floats/lane via float4.
//   u      = mu + sigma*eps[row]          (row scalar)
//   phi    = Phi(u) = normcdff(u)         (row scalar)
//   z[k]   = Phi^{-1}( clip(U,1e-7,1-1e-7) * phi )
//   z[cnew]= u
// ---------------------------------------------------------------------------
__global__ void __launch_bounds__(256, 8)
k_main(const int*   __restrict__ C,
       const float* __restrict__ eps,
       const float* __restrict__ U,
       const float* __restrict__ mu,
       const float* __restrict__ sigma,
       float*       __restrict__ out,
       int n_rows)
{
    int gwarp = (blockIdx.x * blockDim.x + threadIdx.x) >> 5;
    int lane  = threadIdx.x & 31;
    if (gwarp >= n_rows) return;

    const int row = gwarp;

    // Row scalars: same-address loads across the warp -> single broadcast each.
    float mu_v    = __ldg(mu);
    float sg_v    = __ldg(sigma);
    float u       = fmaf(sg_v, __ldg(eps + row), mu_v);
    int   cnew    = g_rank[__ldg(C + row)];
    float phi     = normcdff(u);

    const float LO = 1e-7f;
    const float HI = 1.0f - 1e-7f;   // matches f32 rounding of jnp clip bound

    size_t base = (size_t)row * KDIM;
    float4 uv = __ldg(reinterpret_cast<const float4*>(U + base) + lane);

    int kbase = lane * 4;

    float4 z;
    {
        float x = fminf(fmaxf(uv.x, LO), HI) * phi;
        z.x = (kbase + 0 == cnew) ? u : normcdfinvf(x);
    }
    {
        float x = fminf(fmaxf(uv.y, LO), HI) * phi;
        z.y = (kbase + 1 == cnew) ? u : normcdfinvf(x);
    }
    {
        float x = fminf(fmaxf(uv.z, LO), HI) * phi;
        z.z = (kbase + 2 == cnew) ? u : normcdfinvf(x);
    }
    {
        float x = fminf(fmaxf(uv.w, LO), HI) * phi;
        z.w = (kbase + 3 == cnew) ? u : normcdfinvf(x);
    }

    reinterpret_cast<float4*>(out + base)[lane] = z;
}

// ---------------------------------------------------------------------------
// Launch. Inputs per metadata order: C, eps, U, mu, sigma.
// ---------------------------------------------------------------------------
extern "C" void kernel_launch(void* const* d_in, const int* in_sizes, int n_in,
                              void* d_out, int out_size)
{
    const int*   C     = (const int*)  d_in[0];
    const float* eps   = (const float*)d_in[1];
    const float* U     = (const float*)d_in[2];
    const float* mu    = (const float*)d_in[3];
    const float* sigma = (const float*)d_in[4];
    float*       out   = (float*)d_out;

    const int n_rows = in_sizes[0];          // B*N = 262144

    // Relabel pipeline
    k_zero_present<<<1, KDIM>>>();
    {
        int threads = 256;
        int blocks  = (n_rows + threads - 1) / threads;
        k_scatter_present<<<blocks, threads>>>(C, n_rows);
    }
    k_rank<<<1, KDIM>>>();

    // Main: one warp per row, 8 warps per block
    {
        int threads = 256;
        int warps_per_block = threads / 32;
        int blocks = (n_rows + warps_per_block - 1) / warps_per_block;
        k_main<<<blocks, threads>>>(C, eps, U, mu, sigma, out, n_rows);
    }
}

// round 6
// speedup vs baseline: 1.1432x; 1.1432x over previous
#include <cuda_runtime.h>
#include <cuda_bf16.h>
#include <cstdint>

// Fixed shapes per reference: B=64, N=4096, K=128
#define KDIM 128

// Scratch (no allocations allowed -> __device__ globals; zero-initialized at load,
// and k_rank re-zeroes g_present after use so every call starts from zeros).
__device__ int g_present[KDIM];
__device__ int g_rank[KDIM];

// ---------------------------------------------------------------------------
// Kernel 1: scatter presence from labels C (benign races, all write 1).
// int4-vectorized reads.
// ---------------------------------------------------------------------------
__global__ void k_scatter_present(const int4* __restrict__ C4, int n4) {
    int i = blockIdx.x * blockDim.x + threadIdx.x;
    if (i < n4) {
        int4 c = __ldg(C4 + i);
        g_present[c.x] = 1;
        g_present[c.y] = 1;
        g_present[c.z] = 1;
        g_present[c.w] = 1;
    }
}

// ---------------------------------------------------------------------------
// Kernel 2: rank[v] = #present labels < v (exclusive prefix, 1 block),
// then zero g_present for the next replay (saves a separate zero kernel).
// ---------------------------------------------------------------------------
__global__ void k_rank() {
    __shared__ int p[KDIM];
    int t = threadIdx.x;
    p[t] = g_present[t];
    __syncthreads();
    int r = 0;
    #pragma unroll 8
    for (int j = 0; j < t; ++j) r += p[j];
    g_rank[t] = r;
    g_present[t] = 0;
}

// ---------------------------------------------------------------------------
// Fast ndtri: ndtri(p) = sqrt(2)*erfinv(2p-1), Giles' single-precision erfinv.
// Cancellation-safe: w = -log( (2p) * (2 - 2p) ); 2-a is exact for a in [1,2].
// Max approx error ~1e-6 relative -- threshold is 1e-3.
// ---------------------------------------------------------------------------
__device__ __forceinline__ float ndtri_fast(float p) {
    float a  = 2.0f * p;                                   // exact
    float w  = -__logf(a * (2.0f - a));                    // = -log(1 - x^2)
    float xs = fmaf(1.41421356237f, a, -1.41421356237f);   // sqrt2 * (2p - 1)
    float q;
    if (w < 5.0f) {
        w = w - 2.5f;
        q = 2.81022636e-08f;
        q = fmaf(q, w, 3.43273939e-07f);
        q = fmaf(q, w, -3.5233877e-06f);
        q = fmaf(q, w, -4.39150654e-06f);
        q = fmaf(q, w, 0.00021858087f);
        q = fmaf(q, w, -0.00125372503f);
        q = fmaf(q, w, -0.00417768164f);
        q = fmaf(q, w, 0.246640727f);
        q = fmaf(q, w, 1.50140941f);
    } else {
        w = sqrtf(w) - 3.0f;
        q = -0.000200214257f;
        q = fmaf(q, w, 0.000100950558f);
        q = fmaf(q, w, 0.00134934322f);
        q = fmaf(q, w, -0.00367342844f);
        q = fmaf(q, w, 0.00573950773f);
        q = fmaf(q, w, -0.0076224613f);
        q = fmaf(q, w, 0.00943887047f);
        q = fmaf(q, w, 1.00167406f);
        q = fmaf(q, w, 2.83297682f);
    }
    return q * xs;
}

// ---------------------------------------------------------------------------
// Kernel 3: main. One warp per row (b,i). K=128 -> 4 floats/lane via float4.
//   u       = mu + sigma*eps[row]       (row scalar)
//   phi     = Phi(u)                    (row scalar)
//   z[k]    = ndtri( clip(U,1e-7,1-1e-7) * phi )
//   z[cnew] = u
// Streaming cache hints: U and out are touched exactly once.
// ---------------------------------------------------------------------------
__global__ void __launch_bounds__(256, 8)
k_main(const int*   __restrict__ C,
       const float* __restrict__ eps,
       const float* __restrict__ U,
       const float* __restrict__ mu,
       const float* __restrict__ sigma,
       float*       __restrict__ out,
       int n_rows)
{
    int gwarp = (blockIdx.x * blockDim.x + threadIdx.x) >> 5;
    int lane  = threadIdx.x & 31;
    if (gwarp >= n_rows) return;

    const int row = gwarp;

    // Row scalars (same-address across warp -> broadcast).
    float mu_v = __ldg(mu);
    float sg_v = __ldg(sigma);
    float u    = fmaf(sg_v, __ldg(eps + row), mu_v);
    int   cnew = g_rank[__ldg(C + row)];
    float phi  = normcdff(u);

    const float LO = 1e-7f;
    const float HI = 1.0f - 1e-7f;

    size_t base = (size_t)row * KDIM;
    float4 uv = __ldcs(reinterpret_cast<const float4*>(U + base) + lane);

    int kbase = lane * 4;

    float4 z;
    {
        float x = fminf(fmaxf(uv.x, LO), HI) * phi;
        z.x = (kbase + 0 == cnew) ? u : ndtri_fast(x);
    }
    {
        float x = fminf(fmaxf(uv.y, LO), HI) * phi;
        z.y = (kbase + 1 == cnew) ? u : ndtri_fast(x);
    }
    {
        float x = fminf(fmaxf(uv.z, LO), HI) * phi;
        z.z = (kbase + 2 == cnew) ? u : ndtri_fast(x);
    }
    {
        float x = fminf(fmaxf(uv.w, LO), HI) * phi;
        z.w = (kbase + 3 == cnew) ? u : ndtri_fast(x);
    }

    __stcs(reinterpret_cast<float4*>(out + base) + lane, z);
}

// ---------------------------------------------------------------------------
// Launch. Inputs per metadata order: C, eps, U, mu, sigma.
// ---------------------------------------------------------------------------
extern "C" void kernel_launch(void* const* d_in, const int* in_sizes, int n_in,
                              void* d_out, int out_size)
{
    const int*   C     = (const int*)  d_in[0];
    const float* eps   = (const float*)d_in[1];
    const float* U     = (const float*)d_in[2];
    const float* mu    = (const float*)d_in[3];
    const float* sigma = (const float*)d_in[4];
    float*       out   = (float*)d_out;

    const int n_rows = in_sizes[0];          // B*N = 262144

    // Relabel pipeline (g_present starts zeroed; k_rank re-zeroes it).
    {
        int n4 = n_rows / 4;
        int threads = 256;
        int blocks  = (n4 + threads - 1) / threads;
        k_scatter_present<<<blocks, threads>>>((const int4*)C, n4);
    }
    k_rank<<<1, KDIM>>>();

    // Main: one warp per row, 8 warps per block.
    {
        int threads = 256;
        int warps_per_block = threads / 32;
        int blocks = (n_rows + warps_per_block - 1) / warps_per_block;
        k_main<<<blocks, threads>>>(C, eps, U, mu, sigma, out, n_rows);
    }
}